// round 1
// baseline (speedup 1.0000x reference)
#include <cuda_runtime.h>
#include <math.h>

// Problem constants
#define T_SEQ   2048
#define BATCH   2
#define CDIM    2048
#define NHEADS  16
#define KHEADS  4
#define HDIM    128
#define BT      (BATCH*T_SEQ)          // 4096 tokens
#define QSTRIDE (NHEADS*HDIM)          // 2048
#define KSTRIDE (KHEADS*HDIM)          // 512

// Scratch (device globals: allocation-free per harness rules)
__device__ float g_Q[(size_t)BT*QSTRIDE];
__device__ float g_K[(size_t)BT*KSTRIDE];
__device__ float g_V[(size_t)BT*KSTRIDE];
__device__ float g_E[(size_t)BT*QSTRIDE];
__device__ float g_sin[T_SEQ*64];
__device__ float g_cos[T_SEQ*64];

// ---------------------------------------------------------------------------
// RoPE sine/cosine table (double precision for accuracy vs reference)
// ---------------------------------------------------------------------------
__global__ void rope_table_kernel(float* __restrict__ sinb, float* __restrict__ cosb){
    int idx = blockIdx.x*blockDim.x + threadIdx.x;
    if (idx >= T_SEQ*64) return;
    int t = idx >> 6, i = idx & 63;
    double inv = exp(-log(10000.0) * (double)(2*i) / 128.0);
    double a = (double)t * inv;
    sinb[idx] = (float)sin(a);
    cosb[idx] = (float)cos(a);
}

// ---------------------------------------------------------------------------
// In-place RoPE on projected Q or K. heads in {16, 4}.
// ---------------------------------------------------------------------------
__global__ void rope_apply_kernel(float* __restrict__ buf,
                                  const float* __restrict__ sinb,
                                  const float* __restrict__ cosb, int heads){
    int idx = blockIdx.x*blockDim.x + threadIdx.x;
    int hv = heads << 6;            // pairs per token
    int total = BT * hv;
    if (idx >= total) return;
    int i = idx & 63;
    int n = (idx >> 6) % heads;
    int row = idx / hv;             // token index (b*T + t)
    int t = row & (T_SEQ-1);
    size_t base = (size_t)row*heads*HDIM + (size_t)n*HDIM + i;
    float x1 = buf[base], x2 = buf[base+64];
    float c = cosb[(t<<6)+i], s = sinb[(t<<6)+i];
    buf[base]     = x1*c - x2*s;
    buf[base+64]  = x2*c + x1*s;
}

// ---------------------------------------------------------------------------
// SGEMM: C[M,N] = A[M,Kd] * B[Kd,N], all row-major fp32.
// Block tile 128x128, K tile 16, 256 threads, 8x8 per thread.
// All dims here are multiples of tile sizes (M=4096, N in {512,2048}, Kd=2048).
// ---------------------------------------------------------------------------
__global__ __launch_bounds__(256) void sgemm128_kernel(const float* __restrict__ A,
                                                       const float* __restrict__ Bm,
                                                       float* __restrict__ C,
                                                       int N, int Kd){
    __shared__ float As[16][128];   // transposed A tile: As[k][m]
    __shared__ float Bs[16][128];   // Bs[k][n]
    int tid = threadIdx.x;
    int tx = tid & 15, ty = tid >> 4;
    const float* Ag = A + (size_t)(blockIdx.y*128)*Kd;
    const float* Bg = Bm + blockIdx.x*128;
    float acc[8][8];
    #pragma unroll
    for (int i=0;i<8;i++)
        #pragma unroll
        for (int j=0;j<8;j++) acc[i][j]=0.f;

    for (int k0=0; k0<Kd; k0+=16){
        #pragma unroll
        for (int u=0;u<2;u++){
            int f = tid + u*256;
            // A tile: 128 rows x 16 cols; f indexes float4 (row = f/4, kq = f%4)
            int r  = f >> 2, kq = f & 3;
            float4 a4 = *(const float4*)(Ag + (size_t)r*Kd + k0 + kq*4);
            As[kq*4+0][r]=a4.x; As[kq*4+1][r]=a4.y; As[kq*4+2][r]=a4.z; As[kq*4+3][r]=a4.w;
            // B tile: 16 rows x 128 cols; f indexes float4 (row = f/32, col4 = f%32)
            int rb = f >> 5, c4 = f & 31;
            float4 b4 = *(const float4*)(Bg + (size_t)(k0+rb)*N + c4*4);
            *(float4*)&Bs[rb][c4*4] = b4;
        }
        __syncthreads();
        #pragma unroll
        for (int k=0;k<16;k++){
            float a[8], b[8];
            *(float4*)(a)   = *(const float4*)&As[k][ty*8];
            *(float4*)(a+4) = *(const float4*)&As[k][ty*8+4];
            *(float4*)(b)   = *(const float4*)&Bs[k][tx*8];
            *(float4*)(b+4) = *(const float4*)&Bs[k][tx*8+4];
            #pragma unroll
            for (int i=0;i<8;i++)
                #pragma unroll
                for (int j=0;j<8;j++)
                    acc[i][j] += a[i]*b[j];
        }
        __syncthreads();
    }
    float* Cg = C + (size_t)(blockIdx.y*128 + ty*8)*N + blockIdx.x*128 + tx*8;
    #pragma unroll
    for (int i=0;i<8;i++){
        float4 c0 = make_float4(acc[i][0],acc[i][1],acc[i][2],acc[i][3]);
        float4 c1 = make_float4(acc[i][4],acc[i][5],acc[i][6],acc[i][7]);
        *(float4*)(Cg + (size_t)i*N)     = c0;
        *(float4*)(Cg + (size_t)i*N + 4) = c1;
    }
}

// ---------------------------------------------------------------------------
// Flash attention, fp32, 64 query rows x 64 key cols per tile, HDIM=128.
// tanh softcap(50), causal (diagonal-tile-only masking), online softmax.
// Grid: (T/64, NHEADS, BATCH), 256 threads.
// ---------------------------------------------------------------------------
#define QK_ST 129   // padded stride for Qs/Ks (2-way conflict max on K reads)
#define V_ST  132   // padded stride for Vs (float4-aligned)
#define S_ST  68
#define FLASH_SMEM ((64*QK_ST*2 + 64*V_ST + 64*S_ST + 192)*4)

__global__ __launch_bounds__(256,1) void flash_kernel(const float* __restrict__ Q,
                                                      const float* __restrict__ Kb,
                                                      const float* __restrict__ Vb,
                                                      float* __restrict__ E){
    extern __shared__ float sm[];
    float* Qs   = sm;
    float* Ks   = Qs + 64*QK_ST;
    float* Vs   = Ks + 64*QK_ST;
    float* Ss   = Vs + 64*V_ST;
    float* mrow = Ss + 64*S_ST;
    float* lrow = mrow + 64;
    float* frow = lrow + 64;

    int b = blockIdx.z, n = blockIdx.y;
    int q0 = (gridDim.x - 1 - (int)blockIdx.x) * 64;  // heavy blocks first
    int kh = n >> 2;  // G = 4
    int tid = threadIdx.x;
    int tx = tid & 15, ty = tid >> 4;

    const float scale = 0.08838834764831845f;  // 1/sqrt(128)
    for (int i = tid; i < 64*HDIM; i += 256){
        int r = i >> 7, c = i & 127;
        Qs[r*QK_ST + c] = Q[((size_t)(b*T_SEQ + q0 + r))*QSTRIDE + n*HDIM + c] * scale;
    }
    if (tid < 64){ mrow[tid] = -INFINITY; lrow[tid] = 0.f; }

    float acc[4][8];
    #pragma unroll
    for (int i=0;i<4;i++)
        #pragma unroll
        for (int j=0;j<8;j++) acc[i][j]=0.f;

    int ntiles = q0/64 + 1;
    for (int kt=0; kt<ntiles; kt++){
        int k0 = kt*64;
        __syncthreads();   // protects Ks/Vs/Ss consumers of previous iter + init
        for (int i=tid; i<64*HDIM; i+=256){
            int r = i>>7, c = i&127;
            size_t base = ((size_t)(b*T_SEQ + k0 + r))*KSTRIDE + (size_t)kh*HDIM + c;
            Ks[r*QK_ST + c] = Kb[base];
            Vs[r*V_ST  + c] = Vb[base];
        }
        __syncthreads();

        // S = Qs * Ks^T  (each thread 4x4 of the 64x64 tile)
        float s[4][4];
        #pragma unroll
        for(int i=0;i<4;i++)
            #pragma unroll
            for(int j=0;j<4;j++) s[i][j]=0.f;
        #pragma unroll 4
        for (int kk=0; kk<HDIM; kk++){
            float qv[4], kv[4];
            #pragma unroll
            for(int i=0;i<4;i++) qv[i]=Qs[(ty*4+i)*QK_ST+kk];
            #pragma unroll
            for(int j=0;j<4;j++) kv[j]=Ks[(tx*4+j)*QK_ST+kk];
            #pragma unroll
            for(int i=0;i<4;i++)
                #pragma unroll
                for(int j=0;j<4;j++)
                    s[i][j] += qv[i]*kv[j];
        }
        #pragma unroll
        for(int i=0;i<4;i++)
            #pragma unroll
            for(int j=0;j<4;j++)
                Ss[(ty*4+i)*S_ST + tx*4+j] = s[i][j];
        __syncthreads();

        // Row softmax pass: 4 threads per row, 16 cols each
        {
            int r  = tid >> 2;
            int c0 = (tid & 3) << 4;
            int qi = q0 + r;
            float mold = mrow[r];
            float rmax = -INFINITY;
            #pragma unroll 4
            for (int c=c0; c<c0+16; c++){
                float lv;
                if (k0 + c <= qi) lv = 50.f * tanhf(Ss[r*S_ST+c]*0.02f);
                else              lv = -INFINITY;
                Ss[r*S_ST+c] = lv;
                rmax = fmaxf(rmax, lv);
            }
            rmax = fmaxf(rmax, __shfl_xor_sync(0xffffffffu, rmax, 1));
            rmax = fmaxf(rmax, __shfl_xor_sync(0xffffffffu, rmax, 2));
            float newm = fmaxf(mold, rmax);
            float sum = 0.f;
            #pragma unroll 4
            for (int c=c0; c<c0+16; c++){
                float p = __expf(Ss[r*S_ST+c] - newm);
                Ss[r*S_ST+c] = p;
                sum += p;
            }
            sum += __shfl_xor_sync(0xffffffffu, sum, 1);
            sum += __shfl_xor_sync(0xffffffffu, sum, 2);
            if ((tid & 3) == 0){
                float f = __expf(mold - newm);   // exp(-inf)=0 on first tile
                lrow[r] = lrow[r]*f + sum;
                mrow[r] = newm;
                frow[r] = f;
            }
        }
        __syncthreads();

        // acc = acc*f + P @ V   (each thread 4 rows x 8 cols of 64x128 output)
        #pragma unroll
        for (int i=0;i<4;i++){
            float f = frow[ty*4+i];
            #pragma unroll
            for (int j=0;j<8;j++) acc[i][j] *= f;
        }
        #pragma unroll 2
        for (int kk=0; kk<64; kk++){
            float v0[4], v1[4];
            *(float4*)v0 = *(const float4*)&Vs[kk*V_ST + tx*8];
            *(float4*)v1 = *(const float4*)&Vs[kk*V_ST + tx*8 + 4];
            #pragma unroll
            for (int i=0;i<4;i++){
                float p = Ss[(ty*4+i)*S_ST + kk];
                acc[i][0]+=p*v0[0]; acc[i][1]+=p*v0[1]; acc[i][2]+=p*v0[2]; acc[i][3]+=p*v0[3];
                acc[i][4]+=p*v1[0]; acc[i][5]+=p*v1[1]; acc[i][6]+=p*v1[2]; acc[i][7]+=p*v1[3];
            }
        }
    }

    // lrow final values were written before the last in-loop __syncthreads
    #pragma unroll
    for (int i=0;i<4;i++){
        float inv = 1.f / lrow[ty*4+i];
        size_t base = ((size_t)(b*T_SEQ + q0 + ty*4 + i))*QSTRIDE + (size_t)n*HDIM + tx*8;
        #pragma unroll
        for (int j=0;j<8;j++) E[base+j] = acc[i][j]*inv;
    }
}

// ---------------------------------------------------------------------------
// Launcher
// ---------------------------------------------------------------------------
extern "C" void kernel_launch(void* const* d_in, const int* in_sizes, int n_in,
                              void* d_out, int out_size){
    (void)in_sizes; (void)n_in; (void)out_size;
    const float* x  = (const float*)d_in[0];
    const float* wq = (const float*)d_in[1];
    const float* wk = (const float*)d_in[2];
    const float* wv = (const float*)d_in[3];
    const float* wo = (const float*)d_in[4];
    float* out = (float*)d_out;

    float *Qb,*Kb,*Vb,*Eb,*sinb,*cosb;
    cudaGetSymbolAddress((void**)&Qb,   g_Q);
    cudaGetSymbolAddress((void**)&Kb,   g_K);
    cudaGetSymbolAddress((void**)&Vb,   g_V);
    cudaGetSymbolAddress((void**)&Eb,   g_E);
    cudaGetSymbolAddress((void**)&sinb, g_sin);
    cudaGetSymbolAddress((void**)&cosb, g_cos);
    cudaFuncSetAttribute(flash_kernel, cudaFuncAttributeMaxDynamicSharedMemorySize, FLASH_SMEM);

    rope_table_kernel<<<(T_SEQ*64 + 255)/256, 256>>>(sinb, cosb);

    sgemm128_kernel<<<dim3(QSTRIDE/128, BT/128), 256>>>(x, wq, Qb, QSTRIDE, CDIM);
    sgemm128_kernel<<<dim3(KSTRIDE/128, BT/128), 256>>>(x, wk, Kb, KSTRIDE, CDIM);
    sgemm128_kernel<<<dim3(KSTRIDE/128, BT/128), 256>>>(x, wv, Vb, KSTRIDE, CDIM);

    rope_apply_kernel<<<(BT*NHEADS*64 + 255)/256, 256>>>(Qb, sinb, cosb, NHEADS);
    rope_apply_kernel<<<(BT*KHEADS*64 + 255)/256, 256>>>(Kb, sinb, cosb, KHEADS);

    flash_kernel<<<dim3(T_SEQ/64, NHEADS, BATCH), 256, FLASH_SMEM>>>(Qb, Kb, Vb, Eb);

    sgemm128_kernel<<<dim3(CDIM/128, BT/128), 256>>>(Eb, wo, out, CDIM, CDIM);
}

// round 3
// speedup vs baseline: 1.6850x; 1.6850x over previous
#include <cuda_runtime.h>
#include <math.h>
#include <stdint.h>

// Problem constants
#define T_SEQ   2048
#define BATCH   2
#define CDIM    2048
#define NHEADS  16
#define KHEADS  4
#define HDIM    128
#define BT      (BATCH*T_SEQ)          // 4096 tokens
#define QSTRIDE (NHEADS*HDIM)          // 2048
#define KSTRIDE (KHEADS*HDIM)          // 512

// Scratch (device globals: allocation-free per harness rules)
__device__ float g_Q[(size_t)BT*QSTRIDE];
__device__ float g_K[(size_t)BT*KSTRIDE];
__device__ float g_V[(size_t)BT*KSTRIDE];
__device__ float g_E[(size_t)BT*QSTRIDE];
__device__ float g_Xr[(size_t)BT*CDIM];          // x rounded to tf32
__device__ float g_WTq[(size_t)QSTRIDE*CDIM];    // W^T, tf32-rounded
__device__ float g_WTk[(size_t)KSTRIDE*CDIM];
__device__ float g_WTv[(size_t)KSTRIDE*CDIM];
__device__ float g_WTo[(size_t)CDIM*QSTRIDE];
__device__ float g_sin[T_SEQ*64];
__device__ float g_cos[T_SEQ*64];

// ---------------------------------------------------------------------------
// Helpers
// ---------------------------------------------------------------------------
__device__ __forceinline__ float rntf32(float x){
    unsigned u;
    asm("cvt.rn.tf32.f32 %0, %1;" : "=r"(u) : "f"(x));
    return __uint_as_float(u);
}

__device__ __forceinline__ uint32_t s2u(const void* p){
    uint32_t a;
    asm("{ .reg .u64 t; cvta.to.shared.u64 t, %1; cvt.u32.u64 %0, t; }" : "=r"(a) : "l"(p));
    return a;
}

__device__ __forceinline__ void cpasync16(uint32_t dst, const void* src){
    asm volatile("cp.async.cg.shared.global [%0], [%1], 16;" :: "r"(dst), "l"(src));
}

// mma.sync tf32: D(16x8) += A(16x8) * B(8x8)
__device__ __forceinline__ void mma1688(float* c, const uint32_t* a, const uint32_t* b){
    asm volatile(
        "mma.sync.aligned.m16n8k8.row.col.f32.tf32.tf32.f32 "
        "{%0,%1,%2,%3}, {%4,%5,%6,%7}, {%8,%9}, {%0,%1,%2,%3};"
        : "+f"(c[0]), "+f"(c[1]), "+f"(c[2]), "+f"(c[3])
        : "r"(a[0]), "r"(a[1]), "r"(a[2]), "r"(a[3]), "r"(b[0]), "r"(b[1]));
}

// ---------------------------------------------------------------------------
// RoPE sine/cosine table (double precision)
// ---------------------------------------------------------------------------
__global__ void rope_table_kernel(float* __restrict__ sinb, float* __restrict__ cosb){
    int idx = blockIdx.x*blockDim.x + threadIdx.x;
    if (idx >= T_SEQ*64) return;
    int t = idx >> 6, i = idx & 63;
    double inv = exp(-log(10000.0) * (double)(2*i) / 128.0);
    double a = (double)t * inv;
    sinb[idx] = (float)sin(a);
    cosb[idx] = (float)cos(a);
}

// ---------------------------------------------------------------------------
// In-place RoPE
// ---------------------------------------------------------------------------
__global__ void rope_apply_kernel(float* __restrict__ buf,
                                  const float* __restrict__ sinb,
                                  const float* __restrict__ cosb, int heads){
    int idx = blockIdx.x*blockDim.x + threadIdx.x;
    int hv = heads << 6;
    int total = BT * hv;
    if (idx >= total) return;
    int i = idx & 63;
    int n = (idx >> 6) % heads;
    int row = idx / hv;
    int t = row & (T_SEQ-1);
    size_t base = (size_t)row*heads*HDIM + (size_t)n*HDIM + i;
    float x1 = buf[base], x2 = buf[base+64];
    float c = cosb[(t<<6)+i], s = sinb[(t<<6)+i];
    buf[base]     = x1*c - x2*s;
    buf[base+64]  = x2*c + x1*s;
}

// ---------------------------------------------------------------------------
// Round fp32 array to tf32 (RN), float4 granularity. n multiple of 4.
// ---------------------------------------------------------------------------
__global__ void round_tf32_kernel(const float* __restrict__ in, float* __restrict__ out, int n4){
    int i = blockIdx.x*blockDim.x + threadIdx.x;
    if (i >= n4) return;
    float4 v = ((const float4*)in)[i];
    v.x = rntf32(v.x); v.y = rntf32(v.y); v.z = rntf32(v.z); v.w = rntf32(v.w);
    ((float4*)out)[i] = v;
}

// ---------------------------------------------------------------------------
// Transpose + round: out[n*Kd + k] = rn_tf32(in[k*N + n]).  in: [Kd, N]
// grid (N/32, Kd/32), block (32, 8)
// ---------------------------------------------------------------------------
__global__ void transpose_round_kernel(const float* __restrict__ in, float* __restrict__ out,
                                       int Kd, int N){
    __shared__ float tile[32][33];
    int n0 = blockIdx.x*32, k0 = blockIdx.y*32;
    int tx = threadIdx.x, ty = threadIdx.y;
    #pragma unroll
    for (int i=ty; i<32; i+=8)
        tile[i][tx] = in[(size_t)(k0+i)*N + n0 + tx];
    __syncthreads();
    #pragma unroll
    for (int i=ty; i<32; i+=8)
        out[(size_t)(n0+i)*Kd + k0 + tx] = rntf32(tile[tx][i]);
}

// ---------------------------------------------------------------------------
// mma.sync tf32 GEMM: C[M, Nout] = A[M, 2048] * Bt[Nout, 2048]^T
// Block 128x128, K-tile 32, 3-stage cp.async pipeline, 256 threads (8 warps 2x4).
// Smem tiles stored swizzled: float index = row*32 + (col ^ ((row&7)<<2)).
// grid (Nout/128, M/128)
// ---------------------------------------------------------------------------
#define GST          3
#define STAGE_FLOATS 8192                 // A 128x32 + B 128x32
#define GEMM_SMEM    (GST*STAGE_FLOATS*4) // 98304 bytes

__global__ __launch_bounds__(256) void gemm_mma_kernel(const float* __restrict__ A,
                                                       const float* __restrict__ Bt,
                                                       float* __restrict__ C, int Nout){
    extern __shared__ float sm[];
    int tid  = threadIdx.x;
    int wid  = tid >> 5, lane = tid & 31;
    int gid  = lane >> 2, tg = lane & 3;        // group id (0..7), thread-in-group (0..3)
    int wm   = (wid >> 2) * 64;                 // warp M offset within block
    int wn   = (wid & 3) * 32;                  // warp N offset within block
    int bM   = blockIdx.y, bN = blockIdx.x;
    uint32_t smu = s2u(sm);

    const float* Ag = A  + (size_t)bM*128*CDIM;
    const float* Bg = Bt + (size_t)bN*128*CDIM;
    const int KT = CDIM/32;                     // 64 k-tiles

    // cp.async of one 32-k-tile into stage s (2048 16B chunks, 8 per thread)
    auto load_stage = [&](int s, int kt){
        uint32_t base = smu + (uint32_t)s*STAGE_FLOATS*4;
        #pragma unroll
        for (int u=0; u<8; u++){
            int j = tid + u*256;                // 0..2047
            int half = j >> 10;                 // 0 = A, 1 = B
            int jj = j & 1023;
            int row = jj >> 3, col4 = jj & 7;
            uint32_t dst = base + (uint32_t)(half*4096 + row*32 + ((col4*4) ^ ((row&7)<<2)))*4;
            const float* src = (half ? Bg : Ag) + (size_t)row*CDIM + kt*32 + col4*4;
            cpasync16(dst, src);
        }
    };

    float acc[4][4][4];   // [m-tile][n-tile][reg]
    #pragma unroll
    for (int mi=0;mi<4;mi++)
        #pragma unroll
        for (int ni=0;ni<4;ni++)
            #pragma unroll
            for (int r=0;r<4;r++) acc[mi][ni][r]=0.f;

    #pragma unroll
    for (int kt=0; kt<GST-1; kt++){
        load_stage(kt, kt);
        asm volatile("cp.async.commit_group;");
    }

    for (int kt=0; kt<KT; kt++){
        asm volatile("cp.async.wait_group %0;" :: "n"(GST-2));
        __syncthreads();

        int s = kt % GST;
        const float* As = sm + s*STAGE_FLOATS;
        const float* Bs = As + 4096;
        int swz = gid << 2;

        #pragma unroll
        for (int ks=0; ks<4; ks++){
            int cc0 = (ks*8 + tg) ^ swz;
            int cc1 = (ks*8 + tg + 4) ^ swz;
            uint32_t a[4][4], b[4][2];
            #pragma unroll
            for (int mi=0; mi<4; mi++){
                int r0 = wm + mi*16 + gid;
                a[mi][0] = __float_as_uint(As[r0*32 + cc0]);
                a[mi][1] = __float_as_uint(As[(r0+8)*32 + cc0]);
                a[mi][2] = __float_as_uint(As[r0*32 + cc1]);
                a[mi][3] = __float_as_uint(As[(r0+8)*32 + cc1]);
            }
            #pragma unroll
            for (int ni=0; ni<4; ni++){
                int nr = wn + ni*8 + gid;
                b[ni][0] = __float_as_uint(Bs[nr*32 + cc0]);
                b[ni][1] = __float_as_uint(Bs[nr*32 + cc1]);
            }
            #pragma unroll
            for (int mi=0; mi<4; mi++)
                #pragma unroll
                for (int ni=0; ni<4; ni++)
                    mma1688(acc[mi][ni], a[mi], b[ni]);
        }
        __syncthreads();

        int kl = kt + GST - 1;
        if (kl < KT) load_stage(kl % GST, kl);
        asm volatile("cp.async.commit_group;");
    }

    // Epilogue: c0: (gid, 2*tg), c1: (gid, 2*tg+1), c2/c3: rows +8
    #pragma unroll
    for (int mi=0; mi<4; mi++){
        int r0 = bM*128 + wm + mi*16 + gid;
        #pragma unroll
        for (int ni=0; ni<4; ni++){
            int cc = bN*128 + wn + ni*8 + 2*tg;
            *(float2*)(C + (size_t)r0*Nout + cc)     = make_float2(acc[mi][ni][0], acc[mi][ni][1]);
            *(float2*)(C + (size_t)(r0+8)*Nout + cc) = make_float2(acc[mi][ni][2], acc[mi][ni][3]);
        }
    }
}

// ---------------------------------------------------------------------------
// Flash attention, fp32 (tf32-rounds the stored E for the output projection)
// ---------------------------------------------------------------------------
#define QK_ST 129
#define V_ST  132
#define S_ST  68
#define FLASH_SMEM ((64*QK_ST*2 + 64*V_ST + 64*S_ST + 192)*4)

__global__ __launch_bounds__(256,1) void flash_kernel(const float* __restrict__ Q,
                                                      const float* __restrict__ Kb,
                                                      const float* __restrict__ Vb,
                                                      float* __restrict__ E){
    extern __shared__ float sm[];
    float* Qs   = sm;
    float* Ks   = Qs + 64*QK_ST;
    float* Vs   = Ks + 64*QK_ST;
    float* Ss   = Vs + 64*V_ST;
    float* mrow = Ss + 64*S_ST;
    float* lrow = mrow + 64;
    float* frow = lrow + 64;

    int b = blockIdx.z, n = blockIdx.y;
    int q0 = (gridDim.x - 1 - (int)blockIdx.x) * 64;
    int kh = n >> 2;
    int tid = threadIdx.x;
    int tx = tid & 15, ty = tid >> 4;

    const float scale = 0.08838834764831845f;
    for (int i = tid; i < 64*HDIM; i += 256){
        int r = i >> 7, c = i & 127;
        Qs[r*QK_ST + c] = Q[((size_t)(b*T_SEQ + q0 + r))*QSTRIDE + n*HDIM + c] * scale;
    }
    if (tid < 64){ mrow[tid] = -INFINITY; lrow[tid] = 0.f; }

    float acc[4][8];
    #pragma unroll
    for (int i=0;i<4;i++)
        #pragma unroll
        for (int j=0;j<8;j++) acc[i][j]=0.f;

    int ntiles = q0/64 + 1;
    for (int kt=0; kt<ntiles; kt++){
        int k0 = kt*64;
        __syncthreads();
        for (int i=tid; i<64*HDIM; i+=256){
            int r = i>>7, c = i&127;
            size_t base = ((size_t)(b*T_SEQ + k0 + r))*KSTRIDE + (size_t)kh*HDIM + c;
            Ks[r*QK_ST + c] = Kb[base];
            Vs[r*V_ST  + c] = Vb[base];
        }
        __syncthreads();

        float s[4][4];
        #pragma unroll
        for(int i=0;i<4;i++)
            #pragma unroll
            for(int j=0;j<4;j++) s[i][j]=0.f;
        #pragma unroll 4
        for (int kk=0; kk<HDIM; kk++){
            float qv[4], kv[4];
            #pragma unroll
            for(int i=0;i<4;i++) qv[i]=Qs[(ty*4+i)*QK_ST+kk];
            #pragma unroll
            for(int j=0;j<4;j++) kv[j]=Ks[(tx*4+j)*QK_ST+kk];
            #pragma unroll
            for(int i=0;i<4;i++)
                #pragma unroll
                for(int j=0;j<4;j++)
                    s[i][j] += qv[i]*kv[j];
        }
        #pragma unroll
        for(int i=0;i<4;i++)
            #pragma unroll
            for(int j=0;j<4;j++)
                Ss[(ty*4+i)*S_ST + tx*4+j] = s[i][j];
        __syncthreads();

        {
            int r  = tid >> 2;
            int c0 = (tid & 3) << 4;
            int qi = q0 + r;
            float mold = mrow[r];
            float rmax = -INFINITY;
            #pragma unroll 4
            for (int c=c0; c<c0+16; c++){
                float lv;
                if (k0 + c <= qi) lv = 50.f * tanhf(Ss[r*S_ST+c]*0.02f);
                else              lv = -INFINITY;
                Ss[r*S_ST+c] = lv;
                rmax = fmaxf(rmax, lv);
            }
            rmax = fmaxf(rmax, __shfl_xor_sync(0xffffffffu, rmax, 1));
            rmax = fmaxf(rmax, __shfl_xor_sync(0xffffffffu, rmax, 2));
            float newm = fmaxf(mold, rmax);
            float sum = 0.f;
            #pragma unroll 4
            for (int c=c0; c<c0+16; c++){
                float p = __expf(Ss[r*S_ST+c] - newm);
                Ss[r*S_ST+c] = p;
                sum += p;
            }
            sum += __shfl_xor_sync(0xffffffffu, sum, 1);
            sum += __shfl_xor_sync(0xffffffffu, sum, 2);
            if ((tid & 3) == 0){
                float f = __expf(mold - newm);
                lrow[r] = lrow[r]*f + sum;
                mrow[r] = newm;
                frow[r] = f;
            }
        }
        __syncthreads();

        #pragma unroll
        for (int i=0;i<4;i++){
            float f = frow[ty*4+i];
            #pragma unroll
            for (int j=0;j<8;j++) acc[i][j] *= f;
        }
        #pragma unroll 2
        for (int kk=0; kk<64; kk++){
            float v0[4], v1[4];
            *(float4*)v0 = *(const float4*)&Vs[kk*V_ST + tx*8];
            *(float4*)v1 = *(const float4*)&Vs[kk*V_ST + tx*8 + 4];
            #pragma unroll
            for (int i=0;i<4;i++){
                float p = Ss[(ty*4+i)*S_ST + kk];
                acc[i][0]+=p*v0[0]; acc[i][1]+=p*v0[1]; acc[i][2]+=p*v0[2]; acc[i][3]+=p*v0[3];
                acc[i][4]+=p*v1[0]; acc[i][5]+=p*v1[1]; acc[i][6]+=p*v1[2]; acc[i][7]+=p*v1[3];
            }
        }
    }

    #pragma unroll
    for (int i=0;i<4;i++){
        float inv = 1.f / lrow[ty*4+i];
        size_t base = ((size_t)(b*T_SEQ + q0 + ty*4 + i))*QSTRIDE + (size_t)n*HDIM + tx*8;
        #pragma unroll
        for (int j=0;j<8;j++) E[base+j] = rntf32(acc[i][j]*inv);
    }
}

// ---------------------------------------------------------------------------
// Launcher
// ---------------------------------------------------------------------------
extern "C" void kernel_launch(void* const* d_in, const int* in_sizes, int n_in,
                              void* d_out, int out_size){
    (void)in_sizes; (void)n_in; (void)out_size;
    const float* x  = (const float*)d_in[0];
    const float* wq = (const float*)d_in[1];
    const float* wk = (const float*)d_in[2];
    const float* wv = (const float*)d_in[3];
    const float* wo = (const float*)d_in[4];
    float* out = (float*)d_out;

    float *Qb,*Kb,*Vb,*Eb,*Xr,*WTq,*WTk,*WTv,*WTo,*sinb,*cosb;
    cudaGetSymbolAddress((void**)&Qb,   g_Q);
    cudaGetSymbolAddress((void**)&Kb,   g_K);
    cudaGetSymbolAddress((void**)&Vb,   g_V);
    cudaGetSymbolAddress((void**)&Eb,   g_E);
    cudaGetSymbolAddress((void**)&Xr,   g_Xr);
    cudaGetSymbolAddress((void**)&WTq,  g_WTq);
    cudaGetSymbolAddress((void**)&WTk,  g_WTk);
    cudaGetSymbolAddress((void**)&WTv,  g_WTv);
    cudaGetSymbolAddress((void**)&WTo,  g_WTo);
    cudaGetSymbolAddress((void**)&sinb, g_sin);
    cudaGetSymbolAddress((void**)&cosb, g_cos);
    cudaFuncSetAttribute(flash_kernel, cudaFuncAttributeMaxDynamicSharedMemorySize, FLASH_SMEM);
    cudaFuncSetAttribute(gemm_mma_kernel, cudaFuncAttributeMaxDynamicSharedMemorySize, GEMM_SMEM);

    rope_table_kernel<<<(T_SEQ*64 + 255)/256, 256>>>(sinb, cosb);

    // Prepare tf32-rounded operands
    round_tf32_kernel<<<(BT*CDIM/4 + 255)/256, 256>>>(x, Xr, BT*CDIM/4);
    transpose_round_kernel<<<dim3(QSTRIDE/32, CDIM/32), dim3(32,8)>>>(wq, WTq, CDIM, QSTRIDE);
    transpose_round_kernel<<<dim3(KSTRIDE/32, CDIM/32), dim3(32,8)>>>(wk, WTk, CDIM, KSTRIDE);
    transpose_round_kernel<<<dim3(KSTRIDE/32, CDIM/32), dim3(32,8)>>>(wv, WTv, CDIM, KSTRIDE);
    transpose_round_kernel<<<dim3(CDIM/32, QSTRIDE/32), dim3(32,8)>>>(wo, WTo, QSTRIDE, CDIM);

    // Projections (mma.sync tf32)
    gemm_mma_kernel<<<dim3(QSTRIDE/128, BT/128), 256, GEMM_SMEM>>>(Xr, WTq, Qb, QSTRIDE);
    gemm_mma_kernel<<<dim3(KSTRIDE/128, BT/128), 256, GEMM_SMEM>>>(Xr, WTk, Kb, KSTRIDE);
    gemm_mma_kernel<<<dim3(KSTRIDE/128, BT/128), 256, GEMM_SMEM>>>(Xr, WTv, Vb, KSTRIDE);

    rope_apply_kernel<<<(BT*NHEADS*64 + 255)/256, 256>>>(Qb, sinb, cosb, NHEADS);
    rope_apply_kernel<<<(BT*KHEADS*64 + 255)/256, 256>>>(Kb, sinb, cosb, KHEADS);

    flash_kernel<<<dim3(T_SEQ/64, NHEADS, BATCH), 256, FLASH_SMEM>>>(Qb, Kb, Vb, Eb);

    // Output projection (E already tf32-rounded in flash epilogue)
    gemm_mma_kernel<<<dim3(CDIM/128, BT/128), 256, GEMM_SMEM>>>(Eb, WTo, out, CDIM);
}

// round 4
// speedup vs baseline: 4.0405x; 2.3979x over previous
#include <cuda_runtime.h>
#include <math.h>
#include <stdint.h>

// Problem constants
#define T_SEQ   2048
#define BATCH   2
#define CDIM    2048
#define NHEADS  16
#define KHEADS  4
#define HDIM    128
#define BT      (BATCH*T_SEQ)          // 4096 tokens
#define QSTRIDE (NHEADS*HDIM)          // 2048
#define KSTRIDE (KHEADS*HDIM)          // 512

// Scratch (device globals: allocation-free per harness rules)
__device__ float g_Q[(size_t)BT*QSTRIDE];
__device__ float g_K[(size_t)BT*KSTRIDE];
__device__ float g_V[(size_t)BT*KSTRIDE];
__device__ float g_Vt[(size_t)BATCH*KHEADS*HDIM*T_SEQ];   // [(b*4+kh)*128+h][t]
__device__ float g_E[(size_t)BT*QSTRIDE];
__device__ float g_Xr[(size_t)BT*CDIM];          // x rounded to tf32
__device__ float g_WTq[(size_t)QSTRIDE*CDIM];    // W^T, tf32-rounded
__device__ float g_WTk[(size_t)KSTRIDE*CDIM];
__device__ float g_WTv[(size_t)KSTRIDE*CDIM];
__device__ float g_WTo[(size_t)CDIM*QSTRIDE];
__device__ float g_sin[T_SEQ*64];
__device__ float g_cos[T_SEQ*64];

// ---------------------------------------------------------------------------
// Helpers
// ---------------------------------------------------------------------------
__device__ __forceinline__ float rntf32(float x){
    unsigned u;
    asm("cvt.rn.tf32.f32 %0, %1;" : "=r"(u) : "f"(x));
    return __uint_as_float(u);
}

__device__ __forceinline__ uint32_t s2u(const void* p){
    uint32_t a;
    asm("{ .reg .u64 t; cvta.to.shared.u64 t, %1; cvt.u32.u64 %0, t; }" : "=r"(a) : "l"(p));
    return a;
}

__device__ __forceinline__ void cpasync16(uint32_t dst, const void* src){
    asm volatile("cp.async.cg.shared.global [%0], [%1], 16;" :: "r"(dst), "l"(src));
}

// mma.sync tf32: D(16x8) += A(16x8) * B(8x8)
__device__ __forceinline__ void mma1688(float* c, const uint32_t* a, const uint32_t* b){
    asm volatile(
        "mma.sync.aligned.m16n8k8.row.col.f32.tf32.tf32.f32 "
        "{%0,%1,%2,%3}, {%4,%5,%6,%7}, {%8,%9}, {%0,%1,%2,%3};"
        : "+f"(c[0]), "+f"(c[1]), "+f"(c[2]), "+f"(c[3])
        : "r"(a[0]), "r"(a[1]), "r"(a[2]), "r"(a[3]), "r"(b[0]), "r"(b[1]));
}

// ---------------------------------------------------------------------------
// RoPE sine/cosine table (double precision)
// ---------------------------------------------------------------------------
__global__ void rope_table_kernel(float* __restrict__ sinb, float* __restrict__ cosb){
    int idx = blockIdx.x*blockDim.x + threadIdx.x;
    if (idx >= T_SEQ*64) return;
    int t = idx >> 6, i = idx & 63;
    double inv = exp(-log(10000.0) * (double)(2*i) / 128.0);
    double a = (double)t * inv;
    sinb[idx] = (float)sin(a);
    cosb[idx] = (float)cos(a);
}

// ---------------------------------------------------------------------------
// In-place RoPE, output rounded to tf32 (mma operands)
// ---------------------------------------------------------------------------
__global__ void rope_apply_kernel(float* __restrict__ buf,
                                  const float* __restrict__ sinb,
                                  const float* __restrict__ cosb, int heads){
    int idx = blockIdx.x*blockDim.x + threadIdx.x;
    int hv = heads << 6;
    int total = BT * hv;
    if (idx >= total) return;
    int i = idx & 63;
    int n = (idx >> 6) % heads;
    int row = idx / hv;
    int t = row & (T_SEQ-1);
    size_t base = (size_t)row*heads*HDIM + (size_t)n*HDIM + i;
    float x1 = buf[base], x2 = buf[base+64];
    float c = cosb[(t<<6)+i], s = sinb[(t<<6)+i];
    buf[base]     = rntf32(x1*c - x2*s);
    buf[base+64]  = rntf32(x2*c + x1*s);
}

// ---------------------------------------------------------------------------
// Round fp32 array to tf32 (RN)
// ---------------------------------------------------------------------------
__global__ void round_tf32_kernel(const float* __restrict__ in, float* __restrict__ out, int n4){
    int i = blockIdx.x*blockDim.x + threadIdx.x;
    if (i >= n4) return;
    float4 v = ((const float4*)in)[i];
    v.x = rntf32(v.x); v.y = rntf32(v.y); v.z = rntf32(v.z); v.w = rntf32(v.w);
    ((float4*)out)[i] = v;
}

// ---------------------------------------------------------------------------
// Transpose + round: out[n*Kd + k] = rn_tf32(in[k*N + n]).  in: [Kd, N]
// ---------------------------------------------------------------------------
__global__ void transpose_round_kernel(const float* __restrict__ in, float* __restrict__ out,
                                       int Kd, int N){
    __shared__ float tile[32][33];
    int n0 = blockIdx.x*32, k0 = blockIdx.y*32;
    int tx = threadIdx.x, ty = threadIdx.y;
    #pragma unroll
    for (int i=ty; i<32; i+=8)
        tile[i][tx] = in[(size_t)(k0+i)*N + n0 + tx];
    __syncthreads();
    #pragma unroll
    for (int i=ty; i<32; i+=8)
        out[(size_t)(n0+i)*Kd + k0 + tx] = rntf32(tile[tx][i]);
}

// ---------------------------------------------------------------------------
// V transpose: g_V [b*T+t][kh*128+h] -> g_Vt [(b*4+kh)*128+h][t], tf32-rounded
// grid (512/32, 4096/32), block (32,8)
// ---------------------------------------------------------------------------
__global__ void vtrans_kernel(const float* __restrict__ in, float* __restrict__ out){
    __shared__ float tile[32][33];
    int c0 = blockIdx.x*32;   // col in V (kh*128+h)
    int r0 = blockIdx.y*32;   // token row (b*T+t)
    int tx = threadIdx.x, ty = threadIdx.y;
    #pragma unroll
    for (int i=ty; i<32; i+=8)
        tile[i][tx] = in[(size_t)(r0+i)*KSTRIDE + c0 + tx];
    __syncthreads();
    int ob = (r0 >> 11) * KSTRIDE;   // b*512
    int oc = r0 & (T_SEQ-1);
    #pragma unroll
    for (int i=ty; i<32; i+=8)
        out[(size_t)(ob + c0 + i)*T_SEQ + oc + tx] = rntf32(tile[tx][i]);
}

// ---------------------------------------------------------------------------
// mma.sync tf32 GEMM: C[M, Nout] = A[M, 2048] * Bt[Nout, 2048]^T
// ---------------------------------------------------------------------------
#define GST          3
#define STAGE_FLOATS 8192
#define GEMM_SMEM    (GST*STAGE_FLOATS*4)

__global__ __launch_bounds__(256) void gemm_mma_kernel(const float* __restrict__ A,
                                                       const float* __restrict__ Bt,
                                                       float* __restrict__ C, int Nout){
    extern __shared__ float sm[];
    int tid  = threadIdx.x;
    int wid  = tid >> 5, lane = tid & 31;
    int gid  = lane >> 2, tg = lane & 3;
    int wm   = (wid >> 2) * 64;
    int wn   = (wid & 3) * 32;
    int bM   = blockIdx.y, bN = blockIdx.x;
    uint32_t smu = s2u(sm);

    const float* Ag = A  + (size_t)bM*128*CDIM;
    const float* Bg = Bt + (size_t)bN*128*CDIM;
    const int KT = CDIM/32;

    auto load_stage = [&](int s, int kt){
        uint32_t base = smu + (uint32_t)s*STAGE_FLOATS*4;
        #pragma unroll
        for (int u=0; u<8; u++){
            int j = tid + u*256;
            int half = j >> 10;
            int jj = j & 1023;
            int row = jj >> 3, col4 = jj & 7;
            uint32_t dst = base + (uint32_t)(half*4096 + row*32 + ((col4*4) ^ ((row&7)<<2)))*4;
            const float* src = (half ? Bg : Ag) + (size_t)row*CDIM + kt*32 + col4*4;
            cpasync16(dst, src);
        }
    };

    float acc[4][4][4];
    #pragma unroll
    for (int mi=0;mi<4;mi++)
        #pragma unroll
        for (int ni=0;ni<4;ni++)
            #pragma unroll
            for (int r=0;r<4;r++) acc[mi][ni][r]=0.f;

    #pragma unroll
    for (int kt=0; kt<GST-1; kt++){
        load_stage(kt, kt);
        asm volatile("cp.async.commit_group;");
    }

    for (int kt=0; kt<KT; kt++){
        asm volatile("cp.async.wait_group %0;" :: "n"(GST-2));
        __syncthreads();

        int s = kt % GST;
        const float* As = sm + s*STAGE_FLOATS;
        const float* Bs = As + 4096;
        int swz = gid << 2;

        #pragma unroll
        for (int ks=0; ks<4; ks++){
            int cc0 = (ks*8 + tg) ^ swz;
            int cc1 = (ks*8 + tg + 4) ^ swz;
            uint32_t a[4][4], b[4][2];
            #pragma unroll
            for (int mi=0; mi<4; mi++){
                int r0 = wm + mi*16 + gid;
                a[mi][0] = __float_as_uint(As[r0*32 + cc0]);
                a[mi][1] = __float_as_uint(As[(r0+8)*32 + cc0]);
                a[mi][2] = __float_as_uint(As[r0*32 + cc1]);
                a[mi][3] = __float_as_uint(As[(r0+8)*32 + cc1]);
            }
            #pragma unroll
            for (int ni=0; ni<4; ni++){
                int nr = wn + ni*8 + gid;
                b[ni][0] = __float_as_uint(Bs[nr*32 + cc0]);
                b[ni][1] = __float_as_uint(Bs[nr*32 + cc1]);
            }
            #pragma unroll
            for (int mi=0; mi<4; mi++)
                #pragma unroll
                for (int ni=0; ni<4; ni++)
                    mma1688(acc[mi][ni], a[mi], b[ni]);
        }
        __syncthreads();

        int kl = kt + GST - 1;
        if (kl < KT) load_stage(kl % GST, kl);
        asm volatile("cp.async.commit_group;");
    }

    #pragma unroll
    for (int mi=0; mi<4; mi++){
        int r0 = bM*128 + wm + mi*16 + gid;
        #pragma unroll
        for (int ni=0; ni<4; ni++){
            int cc = bN*128 + wn + ni*8 + 2*tg;
            *(float2*)(C + (size_t)r0*Nout + cc)     = make_float2(acc[mi][ni][0], acc[mi][ni][1]);
            *(float2*)(C + (size_t)(r0+8)*Nout + cc) = make_float2(acc[mi][ni][2], acc[mi][ni][3]);
        }
    }
}

// ---------------------------------------------------------------------------
// Flash attention with mma.sync tf32 for QK^T and P*V.
// 128 q-rows x 64 kv per iter, 8 warps (16 q-rows each), online softmax in
// registers, P layout conversion via intra-quad shuffles.
// grid (T/128, NHEADS, BATCH), 256 threads.
// ---------------------------------------------------------------------------
#define BQ 128
#define BK 64
#define QS_ST 132
#define KS_ST 132
#define VT_ST 68
#define FL_SMEM ((BQ*QS_ST + 2*BK*KS_ST + 2*HDIM*VT_ST)*4)   // 204800

__global__ __launch_bounds__(256,1) void flash_mma_kernel(const float* __restrict__ Q,
                                                          const float* __restrict__ Kg,
                                                          const float* __restrict__ Vtg,
                                                          float* __restrict__ E){
    extern __shared__ float sm[];
    float* Qs = sm;                        // [128][132]
    float* KsB = Qs + BQ*QS_ST;            // [2][64][132]
    float* VsB = KsB + 2*BK*KS_ST;         // [2][128][68]
    uint32_t ks_u = s2u(KsB), vs_u = s2u(VsB);

    int b = blockIdx.z, n = blockIdx.y;
    int q0 = ((int)gridDim.x - 1 - (int)blockIdx.x) * BQ;   // heavy first
    int kh = n >> 2;
    int tid = threadIdx.x, wid = tid >> 5, lane = tid & 31;
    int gid = lane >> 2, tg = lane & 3;

    // Load Q tile (once)
    const float* Qg = Q + (size_t)(b*T_SEQ + q0)*QSTRIDE + n*HDIM;
    #pragma unroll
    for (int u=0; u<16; u++){
        int i = tid + u*256;           // float4 index
        int r = i >> 5, c4 = i & 31;
        *(float4*)&Qs[r*QS_ST + c4*4] = *(const float4*)(Qg + (size_t)r*QSTRIDE + c4*4);
    }

    const float* Kgb = Kg + (size_t)(b*T_SEQ)*KSTRIDE + kh*HDIM;
    const float* Vgb = Vtg + (size_t)(b*KHEADS + kh)*HDIM*T_SEQ;

    auto load_tiles = [&](int buf, int k0){
        #pragma unroll
        for (int u=0; u<8; u++){
            int i = tid + u*256;
            int r = i >> 5, c4 = i & 31;       // K: 64 rows x 32 float4
            cpasync16(ks_u + (uint32_t)(buf*BK*KS_ST + r*KS_ST + c4*4)*4,
                      Kgb + (size_t)(k0 + r)*KSTRIDE + c4*4);
        }
        #pragma unroll
        for (int u=0; u<8; u++){
            int i = tid + u*256;
            int h = i >> 4, c4 = i & 15;       // Vt: 128 rows x 16 float4
            cpasync16(vs_u + (uint32_t)(buf*HDIM*VT_ST + h*VT_ST + c4*4)*4,
                      Vgb + (size_t)h*T_SEQ + k0 + c4*4);
        }
    };

    float oacc[16][4];
    #pragma unroll
    for (int ni=0;ni<16;ni++)
        #pragma unroll
        for (int r=0;r<4;r++) oacc[ni][r]=0.f;
    float m0=-INFINITY, m1=-INFINITY, l0=0.f, l1=0.f;

    const float SC1 = 0.08838834764831845f / 50.f;
    int r0g = q0 + wid*16 + gid;
    int r1g = r0g + 8;
    int ntiles = q0/64 + 2;

    load_tiles(0, 0);
    asm volatile("cp.async.commit_group;");

    for (int kt=0; kt<ntiles; kt++){
        int k0 = kt*BK;
        int buf = kt & 1;
        if (kt+1 < ntiles){
            load_tiles((kt+1)&1, (kt+1)*BK);
            asm volatile("cp.async.commit_group;");
            asm volatile("cp.async.wait_group 1;");
        } else {
            asm volatile("cp.async.wait_group 0;");
        }
        __syncthreads();

        // ---- S = Q * K^T (per warp: 16 rows x 64 cols) ----
        float sacc[8][4];
        #pragma unroll
        for (int ni=0;ni<8;ni++)
            #pragma unroll
            for (int r=0;r<4;r++) sacc[ni][r]=0.f;

        const float* Ksm = KsB + buf*BK*KS_ST;
        const float* Qw  = Qs + (wid*16)*QS_ST;
        #pragma unroll
        for (int ks=0; ks<16; ks++){
            uint32_t a[4];
            a[0] = __float_as_uint(Qw[gid*QS_ST     + ks*8+tg]);
            a[1] = __float_as_uint(Qw[(gid+8)*QS_ST + ks*8+tg]);
            a[2] = __float_as_uint(Qw[gid*QS_ST     + ks*8+tg+4]);
            a[3] = __float_as_uint(Qw[(gid+8)*QS_ST + ks*8+tg+4]);
            #pragma unroll
            for (int ni=0; ni<8; ni++){
                uint32_t bb[2];
                bb[0] = __float_as_uint(Ksm[(ni*8+gid)*KS_ST + ks*8+tg]);
                bb[1] = __float_as_uint(Ksm[(ni*8+gid)*KS_ST + ks*8+tg+4]);
                mma1688(sacc[ni], a, bb);
            }
        }

        // ---- softcap + mask + online softmax (registers) ----
        bool masked = (k0 + BK - 1 > q0);
        float vmax0 = -INFINITY, vmax1 = -INFINITY;
        #pragma unroll
        for (int ni=0; ni<8; ni++){
            #pragma unroll
            for (int j=0; j<4; j++){
                float v = 50.f * tanhf(sacc[ni][j] * SC1);
                if (masked){
                    int col = k0 + ni*8 + tg*2 + (j&1);
                    int row = (j<2) ? r0g : r1g;
                    if (col > row) v = -INFINITY;
                }
                sacc[ni][j] = v;
                if (j<2) vmax0 = fmaxf(vmax0, v); else vmax1 = fmaxf(vmax1, v);
            }
        }
        vmax0 = fmaxf(vmax0, __shfl_xor_sync(0xffffffffu, vmax0, 1));
        vmax0 = fmaxf(vmax0, __shfl_xor_sync(0xffffffffu, vmax0, 2));
        vmax1 = fmaxf(vmax1, __shfl_xor_sync(0xffffffffu, vmax1, 1));
        vmax1 = fmaxf(vmax1, __shfl_xor_sync(0xffffffffu, vmax1, 2));

        float newm0 = fmaxf(m0, vmax0), newm1 = fmaxf(m1, vmax1);
        float f0 = __expf(m0 - newm0), f1 = __expf(m1 - newm1);
        float sum0 = 0.f, sum1 = 0.f;
        #pragma unroll
        for (int ni=0; ni<8; ni++){
            float p0 = rntf32(__expf(sacc[ni][0] - newm0));
            float p1 = rntf32(__expf(sacc[ni][1] - newm0));
            float p2 = rntf32(__expf(sacc[ni][2] - newm1));
            float p3 = rntf32(__expf(sacc[ni][3] - newm1));
            sacc[ni][0]=p0; sacc[ni][1]=p1; sacc[ni][2]=p2; sacc[ni][3]=p3;
            sum0 += p0 + p1; sum1 += p2 + p3;
        }
        sum0 += __shfl_xor_sync(0xffffffffu, sum0, 1);
        sum0 += __shfl_xor_sync(0xffffffffu, sum0, 2);
        sum1 += __shfl_xor_sync(0xffffffffu, sum1, 1);
        sum1 += __shfl_xor_sync(0xffffffffu, sum1, 2);
        l0 = l0*f0 + sum0; m0 = newm0;
        l1 = l1*f1 + sum1; m1 = newm1;

        #pragma unroll
        for (int ni=0; ni<16; ni++){
            oacc[ni][0]*=f0; oacc[ni][1]*=f0; oacc[ni][2]*=f1; oacc[ni][3]*=f1;
        }

        // ---- O += P * V (P via quad shuffles, B from Vt smem) ----
        const float* Vsm = VsB + buf*HDIM*VT_ST;
        int srcA = (lane & ~3) | (tg >> 1);
        int srcB = srcA + 2;
        #pragma unroll
        for (int ks=0; ks<8; ks++){
            float x0 = __shfl_sync(0xffffffffu, sacc[ks][0], srcA);
            float x1 = __shfl_sync(0xffffffffu, sacc[ks][1], srcA);
            float x2 = __shfl_sync(0xffffffffu, sacc[ks][2], srcA);
            float x3 = __shfl_sync(0xffffffffu, sacc[ks][3], srcA);
            float y0 = __shfl_sync(0xffffffffu, sacc[ks][0], srcB);
            float y1 = __shfl_sync(0xffffffffu, sacc[ks][1], srcB);
            float y2 = __shfl_sync(0xffffffffu, sacc[ks][2], srcB);
            float y3 = __shfl_sync(0xffffffffu, sacc[ks][3], srcB);
            uint32_t a[4];
            a[0] = __float_as_uint((tg&1) ? x1 : x0);
            a[1] = __float_as_uint((tg&1) ? x3 : x2);
            a[2] = __float_as_uint((tg&1) ? y1 : y0);
            a[3] = __float_as_uint((tg&1) ? y3 : y2);
            #pragma unroll
            for (int ni=0; ni<16; ni++){
                uint32_t bb[2];
                bb[0] = __float_as_uint(Vsm[(ni*8+gid)*VT_ST + ks*8+tg]);
                bb[1] = __float_as_uint(Vsm[(ni*8+gid)*VT_ST + ks*8+tg+4]);
                mma1688(oacc[ni], a, bb);
            }
        }
        __syncthreads();
    }

    // ---- normalize + write E (tf32-rounded for final GEMM) ----
    float inv0 = 1.f / l0, inv1 = 1.f / l1;
    float* E0 = E + (size_t)(b*T_SEQ + r0g)*QSTRIDE + n*HDIM + tg*2;
    float* E1 = E + (size_t)(b*T_SEQ + r1g)*QSTRIDE + n*HDIM + tg*2;
    #pragma unroll
    for (int ni=0; ni<16; ni++){
        *(float2*)(E0 + ni*8) = make_float2(rntf32(oacc[ni][0]*inv0), rntf32(oacc[ni][1]*inv0));
        *(float2*)(E1 + ni*8) = make_float2(rntf32(oacc[ni][2]*inv1), rntf32(oacc[ni][3]*inv1));
    }
}

// ---------------------------------------------------------------------------
// Launcher
// ---------------------------------------------------------------------------
extern "C" void kernel_launch(void* const* d_in, const int* in_sizes, int n_in,
                              void* d_out, int out_size){
    (void)in_sizes; (void)n_in; (void)out_size;
    const float* x  = (const float*)d_in[0];
    const float* wq = (const float*)d_in[1];
    const float* wk = (const float*)d_in[2];
    const float* wv = (const float*)d_in[3];
    const float* wo = (const float*)d_in[4];
    float* out = (float*)d_out;

    float *Qb,*Kb,*Vb,*Vtb,*Eb,*Xr,*WTq,*WTk,*WTv,*WTo,*sinb,*cosb;
    cudaGetSymbolAddress((void**)&Qb,   g_Q);
    cudaGetSymbolAddress((void**)&Kb,   g_K);
    cudaGetSymbolAddress((void**)&Vb,   g_V);
    cudaGetSymbolAddress((void**)&Vtb,  g_Vt);
    cudaGetSymbolAddress((void**)&Eb,   g_E);
    cudaGetSymbolAddress((void**)&Xr,   g_Xr);
    cudaGetSymbolAddress((void**)&WTq,  g_WTq);
    cudaGetSymbolAddress((void**)&WTk,  g_WTk);
    cudaGetSymbolAddress((void**)&WTv,  g_WTv);
    cudaGetSymbolAddress((void**)&WTo,  g_WTo);
    cudaGetSymbolAddress((void**)&sinb, g_sin);
    cudaGetSymbolAddress((void**)&cosb, g_cos);
    cudaFuncSetAttribute(flash_mma_kernel, cudaFuncAttributeMaxDynamicSharedMemorySize, FL_SMEM);
    cudaFuncSetAttribute(gemm_mma_kernel, cudaFuncAttributeMaxDynamicSharedMemorySize, GEMM_SMEM);

    rope_table_kernel<<<(T_SEQ*64 + 255)/256, 256>>>(sinb, cosb);

    // Prepare tf32-rounded operands
    round_tf32_kernel<<<(BT*CDIM/4 + 255)/256, 256>>>(x, Xr, BT*CDIM/4);
    transpose_round_kernel<<<dim3(QSTRIDE/32, CDIM/32), dim3(32,8)>>>(wq, WTq, CDIM, QSTRIDE);
    transpose_round_kernel<<<dim3(KSTRIDE/32, CDIM/32), dim3(32,8)>>>(wk, WTk, CDIM, KSTRIDE);
    transpose_round_kernel<<<dim3(KSTRIDE/32, CDIM/32), dim3(32,8)>>>(wv, WTv, CDIM, KSTRIDE);
    transpose_round_kernel<<<dim3(CDIM/32, QSTRIDE/32), dim3(32,8)>>>(wo, WTo, QSTRIDE, CDIM);

    // Projections (mma.sync tf32)
    gemm_mma_kernel<<<dim3(QSTRIDE/128, BT/128), 256, GEMM_SMEM>>>(Xr, WTq, Qb, QSTRIDE);
    gemm_mma_kernel<<<dim3(KSTRIDE/128, BT/128), 256, GEMM_SMEM>>>(Xr, WTk, Kb, KSTRIDE);
    gemm_mma_kernel<<<dim3(KSTRIDE/128, BT/128), 256, GEMM_SMEM>>>(Xr, WTv, Vb, KSTRIDE);

    rope_apply_kernel<<<(BT*NHEADS*64 + 255)/256, 256>>>(Qb, sinb, cosb, NHEADS);
    rope_apply_kernel<<<(BT*KHEADS*64 + 255)/256, 256>>>(Kb, sinb, cosb, KHEADS);
    vtrans_kernel<<<dim3(KSTRIDE/32, BT/32), dim3(32,8)>>>(Vb, Vtb);

    flash_mma_kernel<<<dim3(T_SEQ/BQ, NHEADS, BATCH), 256, FL_SMEM>>>(Qb, Kb, Vtb, Eb);

    // Output projection
    gemm_mma_kernel<<<dim3(CDIM/128, BT/128), 256, GEMM_SMEM>>>(Eb, WTo, out, CDIM);
}

// round 5
// speedup vs baseline: 4.0429x; 1.0006x over previous
#include <cuda_runtime.h>
#include <math.h>
#include <stdint.h>

// Problem constants
#define T_SEQ   2048
#define BATCH   2
#define CDIM    2048
#define NHEADS  16
#define KHEADS  4
#define HDIM    128
#define BT      (BATCH*T_SEQ)          // 4096 tokens
#define QSTRIDE (NHEADS*HDIM)          // 2048
#define KSTRIDE (KHEADS*HDIM)          // 512

// Scratch (device globals: allocation-free per harness rules)
__device__ float g_Q[(size_t)BT*QSTRIDE];
__device__ float g_K[(size_t)BT*KSTRIDE];
__device__ float g_V[(size_t)BT*KSTRIDE];
__device__ float g_Vt[(size_t)BATCH*KHEADS*HDIM*T_SEQ];   // [(b*4+kh)*128+h][t]
__device__ float g_E[(size_t)BT*QSTRIDE];
__device__ float g_Xr[(size_t)BT*CDIM];          // x rounded to tf32
__device__ float g_WTq[(size_t)QSTRIDE*CDIM];    // W^T, tf32-rounded
__device__ float g_WTk[(size_t)KSTRIDE*CDIM];
__device__ float g_WTv[(size_t)KSTRIDE*CDIM];
__device__ float g_WTo[(size_t)CDIM*QSTRIDE];
__device__ float g_sin[T_SEQ*64];
__device__ float g_cos[T_SEQ*64];

// ---------------------------------------------------------------------------
// Helpers
// ---------------------------------------------------------------------------
__device__ __forceinline__ float rntf32(float x){
    unsigned u;
    asm("cvt.rn.tf32.f32 %0, %1;" : "=r"(u) : "f"(x));
    return __uint_as_float(u);
}

__device__ __forceinline__ uint32_t s2u(const void* p){
    uint32_t a;
    asm("{ .reg .u64 t; cvta.to.shared.u64 t, %1; cvt.u32.u64 %0, t; }" : "=r"(a) : "l"(p));
    return a;
}

__device__ __forceinline__ void cpasync16(uint32_t dst, const void* src){
    asm volatile("cp.async.cg.shared.global [%0], [%1], 16;" :: "r"(dst), "l"(src));
}

// mma.sync tf32: D(16x8) += A(16x8) * B(8x8)
__device__ __forceinline__ void mma1688(float* c, const uint32_t* a, const uint32_t* b){
    asm volatile(
        "mma.sync.aligned.m16n8k8.row.col.f32.tf32.tf32.f32 "
        "{%0,%1,%2,%3}, {%4,%5,%6,%7}, {%8,%9}, {%0,%1,%2,%3};"
        : "+f"(c[0]), "+f"(c[1]), "+f"(c[2]), "+f"(c[3])
        : "r"(a[0]), "r"(a[1]), "r"(a[2]), "r"(a[3]), "r"(b[0]), "r"(b[1]));
}

// ---------------------------------------------------------------------------
// RoPE sine/cosine table (double precision)
// ---------------------------------------------------------------------------
__global__ void rope_table_kernel(float* __restrict__ sinb, float* __restrict__ cosb){
    int idx = blockIdx.x*blockDim.x + threadIdx.x;
    if (idx >= T_SEQ*64) return;
    int t = idx >> 6, i = idx & 63;
    double inv = exp(-log(10000.0) * (double)(2*i) / 128.0);
    double a = (double)t * inv;
    sinb[idx] = (float)sin(a);
    cosb[idx] = (float)cos(a);
}

// ---------------------------------------------------------------------------
// In-place RoPE, output rounded to tf32 (mma operands)
// ---------------------------------------------------------------------------
__global__ void rope_apply_kernel(float* __restrict__ buf,
                                  const float* __restrict__ sinb,
                                  const float* __restrict__ cosb, int heads){
    int idx = blockIdx.x*blockDim.x + threadIdx.x;
    int hv = heads << 6;
    int total = BT * hv;
    if (idx >= total) return;
    int i = idx & 63;
    int n = (idx >> 6) % heads;
    int row = idx / hv;
    int t = row & (T_SEQ-1);
    size_t base = (size_t)row*heads*HDIM + (size_t)n*HDIM + i;
    float x1 = buf[base], x2 = buf[base+64];
    float c = cosb[(t<<6)+i], s = sinb[(t<<6)+i];
    buf[base]     = rntf32(x1*c - x2*s);
    buf[base+64]  = rntf32(x2*c + x1*s);
}

// ---------------------------------------------------------------------------
// Round fp32 array to tf32 (RN)
// ---------------------------------------------------------------------------
__global__ void round_tf32_kernel(const float* __restrict__ in, float* __restrict__ out, int n4){
    int i = blockIdx.x*blockDim.x + threadIdx.x;
    if (i >= n4) return;
    float4 v = ((const float4*)in)[i];
    v.x = rntf32(v.x); v.y = rntf32(v.y); v.z = rntf32(v.z); v.w = rntf32(v.w);
    ((float4*)out)[i] = v;
}

// ---------------------------------------------------------------------------
// Transpose + round: out[n*Kd + k] = rn_tf32(in[k*N + n]).  in: [Kd, N]
// ---------------------------------------------------------------------------
__global__ void transpose_round_kernel(const float* __restrict__ in, float* __restrict__ out,
                                       int Kd, int N){
    __shared__ float tile[32][33];
    int n0 = blockIdx.x*32, k0 = blockIdx.y*32;
    int tx = threadIdx.x, ty = threadIdx.y;
    #pragma unroll
    for (int i=ty; i<32; i+=8)
        tile[i][tx] = in[(size_t)(k0+i)*N + n0 + tx];
    __syncthreads();
    #pragma unroll
    for (int i=ty; i<32; i+=8)
        out[(size_t)(n0+i)*Kd + k0 + tx] = rntf32(tile[tx][i]);
}

// ---------------------------------------------------------------------------
// V transpose: g_V [b*T+t][kh*128+h] -> g_Vt [(b*4+kh)*128+h][t], tf32-rounded
// grid (512/32, 4096/32), block (32,8)
// ---------------------------------------------------------------------------
__global__ void vtrans_kernel(const float* __restrict__ in, float* __restrict__ out){
    __shared__ float tile[32][33];
    int c0 = blockIdx.x*32;   // col in V (kh*128+h)
    int r0 = blockIdx.y*32;   // token row (b*T+t)
    int tx = threadIdx.x, ty = threadIdx.y;
    #pragma unroll
    for (int i=ty; i<32; i+=8)
        tile[i][tx] = in[(size_t)(r0+i)*KSTRIDE + c0 + tx];
    __syncthreads();
    int ob = (r0 >> 11) * KSTRIDE;   // b*512
    int oc = r0 & (T_SEQ-1);
    #pragma unroll
    for (int i=ty; i<32; i+=8)
        out[(size_t)(ob + c0 + i)*T_SEQ + oc + tx] = rntf32(tile[tx][i]);
}

// ---------------------------------------------------------------------------
// mma.sync tf32 GEMM: C[M, Nout] = A[M, 2048] * Bt[Nout, 2048]^T
// ---------------------------------------------------------------------------
#define GST          3
#define STAGE_FLOATS 8192
#define GEMM_SMEM    (GST*STAGE_FLOATS*4)

__global__ __launch_bounds__(256) void gemm_mma_kernel(const float* __restrict__ A,
                                                       const float* __restrict__ Bt,
                                                       float* __restrict__ C, int Nout){
    extern __shared__ float sm[];
    int tid  = threadIdx.x;
    int wid  = tid >> 5, lane = tid & 31;
    int gid  = lane >> 2, tg = lane & 3;
    int wm   = (wid >> 2) * 64;
    int wn   = (wid & 3) * 32;
    int bM   = blockIdx.y, bN = blockIdx.x;
    uint32_t smu = s2u(sm);

    const float* Ag = A  + (size_t)bM*128*CDIM;
    const float* Bg = Bt + (size_t)bN*128*CDIM;
    const int KT = CDIM/32;

    auto load_stage = [&](int s, int kt){
        uint32_t base = smu + (uint32_t)s*STAGE_FLOATS*4;
        #pragma unroll
        for (int u=0; u<8; u++){
            int j = tid + u*256;
            int half = j >> 10;
            int jj = j & 1023;
            int row = jj >> 3, col4 = jj & 7;
            uint32_t dst = base + (uint32_t)(half*4096 + row*32 + ((col4*4) ^ ((row&7)<<2)))*4;
            const float* src = (half ? Bg : Ag) + (size_t)row*CDIM + kt*32 + col4*4;
            cpasync16(dst, src);
        }
    };

    float acc[4][4][4];
    #pragma unroll
    for (int mi=0;mi<4;mi++)
        #pragma unroll
        for (int ni=0;ni<4;ni++)
            #pragma unroll
            for (int r=0;r<4;r++) acc[mi][ni][r]=0.f;

    #pragma unroll
    for (int kt=0; kt<GST-1; kt++){
        load_stage(kt, kt);
        asm volatile("cp.async.commit_group;");
    }

    for (int kt=0; kt<KT; kt++){
        asm volatile("cp.async.wait_group %0;" :: "n"(GST-2));
        __syncthreads();

        int s = kt % GST;
        const float* As = sm + s*STAGE_FLOATS;
        const float* Bs = As + 4096;
        int swz = gid << 2;

        #pragma unroll
        for (int ks=0; ks<4; ks++){
            int cc0 = (ks*8 + tg) ^ swz;
            int cc1 = (ks*8 + tg + 4) ^ swz;
            uint32_t a[4][4], b[4][2];
            #pragma unroll
            for (int mi=0; mi<4; mi++){
                int r0 = wm + mi*16 + gid;
                a[mi][0] = __float_as_uint(As[r0*32 + cc0]);
                a[mi][1] = __float_as_uint(As[(r0+8)*32 + cc0]);
                a[mi][2] = __float_as_uint(As[r0*32 + cc1]);
                a[mi][3] = __float_as_uint(As[(r0+8)*32 + cc1]);
            }
            #pragma unroll
            for (int ni=0; ni<4; ni++){
                int nr = wn + ni*8 + gid;
                b[ni][0] = __float_as_uint(Bs[nr*32 + cc0]);
                b[ni][1] = __float_as_uint(Bs[nr*32 + cc1]);
            }
            #pragma unroll
            for (int mi=0; mi<4; mi++)
                #pragma unroll
                for (int ni=0; ni<4; ni++)
                    mma1688(acc[mi][ni], a[mi], b[ni]);
        }
        __syncthreads();

        int kl = kt + GST - 1;
        if (kl < KT) load_stage(kl % GST, kl);
        asm volatile("cp.async.commit_group;");
    }

    #pragma unroll
    for (int mi=0; mi<4; mi++){
        int r0 = bM*128 + wm + mi*16 + gid;
        #pragma unroll
        for (int ni=0; ni<4; ni++){
            int cc = bN*128 + wn + ni*8 + 2*tg;
            *(float2*)(C + (size_t)r0*Nout + cc)     = make_float2(acc[mi][ni][0], acc[mi][ni][1]);
            *(float2*)(C + (size_t)(r0+8)*Nout + cc) = make_float2(acc[mi][ni][2], acc[mi][ni][3]);
        }
    }
}

// ---------------------------------------------------------------------------
// Flash attention with mma.sync tf32 for QK^T and P*V.
// 128 q-rows x 64 kv per iter, 8 warps (16 q-rows each), online softmax in
// registers, P layout conversion via intra-quad shuffles.
// grid (T/128, NHEADS, BATCH), 256 threads.
// ---------------------------------------------------------------------------
#define BQ 128
#define BK 64
#define QS_ST 132
#define KS_ST 132
#define VT_ST 68
#define FL_SMEM ((BQ*QS_ST + 2*BK*KS_ST + 2*HDIM*VT_ST)*4)   // 204800

__global__ __launch_bounds__(256,1) void flash_mma_kernel(const float* __restrict__ Q,
                                                          const float* __restrict__ Kg,
                                                          const float* __restrict__ Vtg,
                                                          float* __restrict__ E){
    extern __shared__ float sm[];
    float* Qs = sm;                        // [128][132]
    float* KsB = Qs + BQ*QS_ST;            // [2][64][132]
    float* VsB = KsB + 2*BK*KS_ST;         // [2][128][68]
    uint32_t ks_u = s2u(KsB), vs_u = s2u(VsB);

    int b = blockIdx.z, n = blockIdx.y;
    int q0 = ((int)gridDim.x - 1 - (int)blockIdx.x) * BQ;   // heavy first
    int kh = n >> 2;
    int tid = threadIdx.x, wid = tid >> 5, lane = tid & 31;
    int gid = lane >> 2, tg = lane & 3;

    // Load Q tile (once)
    const float* Qg = Q + (size_t)(b*T_SEQ + q0)*QSTRIDE + n*HDIM;
    #pragma unroll
    for (int u=0; u<16; u++){
        int i = tid + u*256;           // float4 index
        int r = i >> 5, c4 = i & 31;
        *(float4*)&Qs[r*QS_ST + c4*4] = *(const float4*)(Qg + (size_t)r*QSTRIDE + c4*4);
    }

    const float* Kgb = Kg + (size_t)(b*T_SEQ)*KSTRIDE + kh*HDIM;
    const float* Vgb = Vtg + (size_t)(b*KHEADS + kh)*HDIM*T_SEQ;

    auto load_tiles = [&](int buf, int k0){
        #pragma unroll
        for (int u=0; u<8; u++){
            int i = tid + u*256;
            int r = i >> 5, c4 = i & 31;       // K: 64 rows x 32 float4
            cpasync16(ks_u + (uint32_t)(buf*BK*KS_ST + r*KS_ST + c4*4)*4,
                      Kgb + (size_t)(k0 + r)*KSTRIDE + c4*4);
        }
        #pragma unroll
        for (int u=0; u<8; u++){
            int i = tid + u*256;
            int h = i >> 4, c4 = i & 15;       // Vt: 128 rows x 16 float4
            cpasync16(vs_u + (uint32_t)(buf*HDIM*VT_ST + h*VT_ST + c4*4)*4,
                      Vgb + (size_t)h*T_SEQ + k0 + c4*4);
        }
    };

    float oacc[16][4];
    #pragma unroll
    for (int ni=0;ni<16;ni++)
        #pragma unroll
        for (int r=0;r<4;r++) oacc[ni][r]=0.f;
    float m0=-INFINITY, m1=-INFINITY, l0=0.f, l1=0.f;

    const float SC1 = 0.08838834764831845f / 50.f;
    int r0g = q0 + wid*16 + gid;
    int r1g = r0g + 8;
    int ntiles = q0/64 + 2;

    load_tiles(0, 0);
    asm volatile("cp.async.commit_group;");

    for (int kt=0; kt<ntiles; kt++){
        int k0 = kt*BK;
        int buf = kt & 1;
        if (kt+1 < ntiles){
            load_tiles((kt+1)&1, (kt+1)*BK);
            asm volatile("cp.async.commit_group;");
            asm volatile("cp.async.wait_group 1;");
        } else {
            asm volatile("cp.async.wait_group 0;");
        }
        __syncthreads();

        // ---- S = Q * K^T (per warp: 16 rows x 64 cols) ----
        float sacc[8][4];
        #pragma unroll
        for (int ni=0;ni<8;ni++)
            #pragma unroll
            for (int r=0;r<4;r++) sacc[ni][r]=0.f;

        const float* Ksm = KsB + buf*BK*KS_ST;
        const float* Qw  = Qs + (wid*16)*QS_ST;
        #pragma unroll
        for (int ks=0; ks<16; ks++){
            uint32_t a[4];
            a[0] = __float_as_uint(Qw[gid*QS_ST     + ks*8+tg]);
            a[1] = __float_as_uint(Qw[(gid+8)*QS_ST + ks*8+tg]);
            a[2] = __float_as_uint(Qw[gid*QS_ST     + ks*8+tg+4]);
            a[3] = __float_as_uint(Qw[(gid+8)*QS_ST + ks*8+tg+4]);
            #pragma unroll
            for (int ni=0; ni<8; ni++){
                uint32_t bb[2];
                bb[0] = __float_as_uint(Ksm[(ni*8+gid)*KS_ST + ks*8+tg]);
                bb[1] = __float_as_uint(Ksm[(ni*8+gid)*KS_ST + ks*8+tg+4]);
                mma1688(sacc[ni], a, bb);
            }
        }

        // ---- softcap + mask + online softmax (registers) ----
        bool masked = (k0 + BK - 1 > q0);
        float vmax0 = -INFINITY, vmax1 = -INFINITY;
        #pragma unroll
        for (int ni=0; ni<8; ni++){
            #pragma unroll
            for (int j=0; j<4; j++){
                float v = 50.f * tanhf(sacc[ni][j] * SC1);
                if (masked){
                    int col = k0 + ni*8 + tg*2 + (j&1);
                    int row = (j<2) ? r0g : r1g;
                    if (col > row) v = -INFINITY;
                }
                sacc[ni][j] = v;
                if (j<2) vmax0 = fmaxf(vmax0, v); else vmax1 = fmaxf(vmax1, v);
            }
        }
        vmax0 = fmaxf(vmax0, __shfl_xor_sync(0xffffffffu, vmax0, 1));
        vmax0 = fmaxf(vmax0, __shfl_xor_sync(0xffffffffu, vmax0, 2));
        vmax1 = fmaxf(vmax1, __shfl_xor_sync(0xffffffffu, vmax1, 1));
        vmax1 = fmaxf(vmax1, __shfl_xor_sync(0xffffffffu, vmax1, 2));

        float newm0 = fmaxf(m0, vmax0), newm1 = fmaxf(m1, vmax1);
        float f0 = __expf(m0 - newm0), f1 = __expf(m1 - newm1);
        float sum0 = 0.f, sum1 = 0.f;
        #pragma unroll
        for (int ni=0; ni<8; ni++){
            float p0 = rntf32(__expf(sacc[ni][0] - newm0));
            float p1 = rntf32(__expf(sacc[ni][1] - newm0));
            float p2 = rntf32(__expf(sacc[ni][2] - newm1));
            float p3 = rntf32(__expf(sacc[ni][3] - newm1));
            sacc[ni][0]=p0; sacc[ni][1]=p1; sacc[ni][2]=p2; sacc[ni][3]=p3;
            sum0 += p0 + p1; sum1 += p2 + p3;
        }
        sum0 += __shfl_xor_sync(0xffffffffu, sum0, 1);
        sum0 += __shfl_xor_sync(0xffffffffu, sum0, 2);
        sum1 += __shfl_xor_sync(0xffffffffu, sum1, 1);
        sum1 += __shfl_xor_sync(0xffffffffu, sum1, 2);
        l0 = l0*f0 + sum0; m0 = newm0;
        l1 = l1*f1 + sum1; m1 = newm1;

        #pragma unroll
        for (int ni=0; ni<16; ni++){
            oacc[ni][0]*=f0; oacc[ni][1]*=f0; oacc[ni][2]*=f1; oacc[ni][3]*=f1;
        }

        // ---- O += P * V (P via quad shuffles, B from Vt smem) ----
        const float* Vsm = VsB + buf*HDIM*VT_ST;
        int srcA = (lane & ~3) | (tg >> 1);
        int srcB = srcA + 2;
        #pragma unroll
        for (int ks=0; ks<8; ks++){
            float x0 = __shfl_sync(0xffffffffu, sacc[ks][0], srcA);
            float x1 = __shfl_sync(0xffffffffu, sacc[ks][1], srcA);
            float x2 = __shfl_sync(0xffffffffu, sacc[ks][2], srcA);
            float x3 = __shfl_sync(0xffffffffu, sacc[ks][3], srcA);
            float y0 = __shfl_sync(0xffffffffu, sacc[ks][0], srcB);
            float y1 = __shfl_sync(0xffffffffu, sacc[ks][1], srcB);
            float y2 = __shfl_sync(0xffffffffu, sacc[ks][2], srcB);
            float y3 = __shfl_sync(0xffffffffu, sacc[ks][3], srcB);
            uint32_t a[4];
            a[0] = __float_as_uint((tg&1) ? x1 : x0);
            a[1] = __float_as_uint((tg&1) ? x3 : x2);
            a[2] = __float_as_uint((tg&1) ? y1 : y0);
            a[3] = __float_as_uint((tg&1) ? y3 : y2);
            #pragma unroll
            for (int ni=0; ni<16; ni++){
                uint32_t bb[2];
                bb[0] = __float_as_uint(Vsm[(ni*8+gid)*VT_ST + ks*8+tg]);
                bb[1] = __float_as_uint(Vsm[(ni*8+gid)*VT_ST + ks*8+tg+4]);
                mma1688(oacc[ni], a, bb);
            }
        }
        __syncthreads();
    }

    // ---- normalize + write E (tf32-rounded for final GEMM) ----
    float inv0 = 1.f / l0, inv1 = 1.f / l1;
    float* E0 = E + (size_t)(b*T_SEQ + r0g)*QSTRIDE + n*HDIM + tg*2;
    float* E1 = E + (size_t)(b*T_SEQ + r1g)*QSTRIDE + n*HDIM + tg*2;
    #pragma unroll
    for (int ni=0; ni<16; ni++){
        *(float2*)(E0 + ni*8) = make_float2(rntf32(oacc[ni][0]*inv0), rntf32(oacc[ni][1]*inv0));
        *(float2*)(E1 + ni*8) = make_float2(rntf32(oacc[ni][2]*inv1), rntf32(oacc[ni][3]*inv1));
    }
}

// ---------------------------------------------------------------------------
// Launcher
// ---------------------------------------------------------------------------
extern "C" void kernel_launch(void* const* d_in, const int* in_sizes, int n_in,
                              void* d_out, int out_size){
    (void)in_sizes; (void)n_in; (void)out_size;
    const float* x  = (const float*)d_in[0];
    const float* wq = (const float*)d_in[1];
    const float* wk = (const float*)d_in[2];
    const float* wv = (const float*)d_in[3];
    const float* wo = (const float*)d_in[4];
    float* out = (float*)d_out;

    float *Qb,*Kb,*Vb,*Vtb,*Eb,*Xr,*WTq,*WTk,*WTv,*WTo,*sinb,*cosb;
    cudaGetSymbolAddress((void**)&Qb,   g_Q);
    cudaGetSymbolAddress((void**)&Kb,   g_K);
    cudaGetSymbolAddress((void**)&Vb,   g_V);
    cudaGetSymbolAddress((void**)&Vtb,  g_Vt);
    cudaGetSymbolAddress((void**)&Eb,   g_E);
    cudaGetSymbolAddress((void**)&Xr,   g_Xr);
    cudaGetSymbolAddress((void**)&WTq,  g_WTq);
    cudaGetSymbolAddress((void**)&WTk,  g_WTk);
    cudaGetSymbolAddress((void**)&WTv,  g_WTv);
    cudaGetSymbolAddress((void**)&WTo,  g_WTo);
    cudaGetSymbolAddress((void**)&sinb, g_sin);
    cudaGetSymbolAddress((void**)&cosb, g_cos);
    cudaFuncSetAttribute(flash_mma_kernel, cudaFuncAttributeMaxDynamicSharedMemorySize, FL_SMEM);
    cudaFuncSetAttribute(gemm_mma_kernel, cudaFuncAttributeMaxDynamicSharedMemorySize, GEMM_SMEM);

    rope_table_kernel<<<(T_SEQ*64 + 255)/256, 256>>>(sinb, cosb);

    // Prepare tf32-rounded operands
    round_tf32_kernel<<<(BT*CDIM/4 + 255)/256, 256>>>(x, Xr, BT*CDIM/4);
    transpose_round_kernel<<<dim3(QSTRIDE/32, CDIM/32), dim3(32,8)>>>(wq, WTq, CDIM, QSTRIDE);
    transpose_round_kernel<<<dim3(KSTRIDE/32, CDIM/32), dim3(32,8)>>>(wk, WTk, CDIM, KSTRIDE);
    transpose_round_kernel<<<dim3(KSTRIDE/32, CDIM/32), dim3(32,8)>>>(wv, WTv, CDIM, KSTRIDE);
    transpose_round_kernel<<<dim3(CDIM/32, QSTRIDE/32), dim3(32,8)>>>(wo, WTo, QSTRIDE, CDIM);

    // Projections (mma.sync tf32)
    gemm_mma_kernel<<<dim3(QSTRIDE/128, BT/128), 256, GEMM_SMEM>>>(Xr, WTq, Qb, QSTRIDE);
    gemm_mma_kernel<<<dim3(KSTRIDE/128, BT/128), 256, GEMM_SMEM>>>(Xr, WTk, Kb, KSTRIDE);
    gemm_mma_kernel<<<dim3(KSTRIDE/128, BT/128), 256, GEMM_SMEM>>>(Xr, WTv, Vb, KSTRIDE);

    rope_apply_kernel<<<(BT*NHEADS*64 + 255)/256, 256>>>(Qb, sinb, cosb, NHEADS);
    rope_apply_kernel<<<(BT*KHEADS*64 + 255)/256, 256>>>(Kb, sinb, cosb, KHEADS);
    vtrans_kernel<<<dim3(KSTRIDE/32, BT/32), dim3(32,8)>>>(Vb, Vtb);

    flash_mma_kernel<<<dim3(T_SEQ/BQ, NHEADS, BATCH), 256, FL_SMEM>>>(Qb, Kb, Vtb, Eb);

    // Output projection
    gemm_mma_kernel<<<dim3(CDIM/128, BT/128), 256, GEMM_SMEM>>>(Eb, WTo, out, CDIM);
}